// round 12
// baseline (speedup 1.0000x reference)
#include <cuda_runtime.h>
#include <math.h>
#include <stdint.h>

#define NEG_SLOPE 0.2f
#define KNN_K 20
#define BATCH 8
#define NPTS 2048
#define CO 64
#define CIN 6
#define ROWS 384
#define NPOINTS (BATCH * NPTS)

__device__ int g_knn[NPOINTS * KNN_K];

typedef unsigned long long u64;

__device__ __forceinline__ void ffma2(u64& d, u64 a, u64 b) {
    asm("fma.rn.f32x2 %0, %1, %2, %0;" : "+l"(d) : "l"(a), "l"(b));
}
__device__ __forceinline__ u64 dup2(float w) {
    u64 r; asm("mov.b64 %0, {%1, %1};" : "=l"(r) : "f"(w)); return r;
}
__device__ __forceinline__ u64 pack2(float lo, float hi) {
    u64 r; asm("mov.b64 %0, {%1, %2};" : "=l"(r) : "f"(lo), "f"(hi)); return r;
}
__device__ __forceinline__ void unpack2(float& lo, float& hi, u64 v) {
    asm("mov.b64 {%0, %1}, %2;" : "=f"(lo), "=f"(hi) : "l"(v));
}

// ===========================================================================
// Kernel 1: KNN. 256 blocks x 512 threads. 64 points/block, 8 segment-threads
// per point (256 j each). Phase A: scalar FMNMX top-20 chain. Merge -> tau.
// Phase B: rescan collect. Rank-based parallel exact selection.
// ===========================================================================
#define KNN_THR 512
#define KNN_PPB 64
#define KSEG 8
#define SEGLEN (NPTS / KSEG)          // 256
#define CAND_CAP 32

#define KOFF_P     0                                      // float4[2048] = 8192
#define KOFF_LIST  (NPTS * 4)                             // [64][8][20] = 10240
#define KOFF_TAU   (KOFF_LIST + KNN_PPB * KSEG * KNN_K)   // 64
#define KOFF_CNT   (KOFF_TAU + KNN_PPB)                   // 64
#define KOFF_CD    (KOFF_CNT + KNN_PPB)                   // [64][32]
#define KOFF_CJ    (KOFF_CD + KNN_PPB * CAND_CAP)         // [64][32]
#define KNN_SMEM_FLOATS (KOFF_CJ + KNN_PPB * CAND_CAP)
#define KNN_SMEM_BYTES (KNN_SMEM_FLOATS * 4)

__global__ __launch_bounds__(KNN_THR) void knn_kernel(const float* __restrict__ x) {
    extern __shared__ float ksm[];
    float4* sP   = (float4*)(ksm + KOFF_P);
    float* sList = ksm + KOFF_LIST;
    float* sTau  = ksm + KOFF_TAU;
    int*   sCnt  = (int*)(ksm + KOFF_CNT);
    float* sCd   = ksm + KOFF_CD;
    int*   sCj   = (int*)(ksm + KOFF_CJ);

    const int b = blockIdx.x >> 5;
    const int chunk = blockIdx.x & 31;
    const float* xb = x + (size_t)b * 3 * NPTS;

    const int t = threadIdx.x;
    for (int j = t; j < NPTS; j += KNN_THR) {
        float a0 = xb[j], a1 = xb[NPTS + j], a2 = xb[2 * NPTS + j];
        float xx = (a0 * a0 + a1 * a1) + a2 * a2;
        sP[j] = make_float4(a0, a1, a2, xx);
    }
    if (t < KNN_PPB) sCnt[t] = 0;
    __syncthreads();

    const int s  = t >> 6;        // segment 0..7 (warp-uniform)
    const int pp = t & 63;
    const int i  = (chunk << 6) + pp;

    float4 cv = sP[i];
    const float c0 = cv.x, c1 = cv.y, c2 = cv.z, cxx = cv.w;

    // ---- Phase A: value-only sorted top-20 ----
    float v[KNN_K];
#pragma unroll
    for (int k = 0; k < KNN_K; k++) v[k] = -INFINITY;

    const int j0 = s * SEGLEN;
#pragma unroll 4
    for (int jj = 0; jj < SEGLEN; jj++) {
        int j = j0 + jj;
        float4 p4 = sP[j];
        float d = c0 * p4.x;
        d = fmaf(c1, p4.y, d);
        d = fmaf(c2, p4.z, d);
        d = 2.0f * d - cxx - p4.w;
        if (d > v[KNN_K - 1]) {
            float c = d;
#pragma unroll
            for (int k = 0; k < KNN_K; k++) {
                float nv = fmaxf(v[k], c);
                c = fminf(v[k], c);
                v[k] = nv;
            }
        }
    }
    {
        float* lp = sList + (pp * KSEG + s) * KNN_K;
#pragma unroll
        for (int k = 0; k < KNN_K; k++) lp[k] = v[k];
    }
    __syncthreads();

    // ---- merge: seg-0 lanes fold in the other 7 lists -> tau ----
    if (s == 0) {
        for (int ss = 1; ss < KSEG; ss++) {
            const float* lp = sList + (pp * KSEG + ss) * KNN_K;
#pragma unroll
            for (int k = 0; k < KNN_K; k++) {
                float d = lp[k];
                if (d > v[KNN_K - 1]) {
                    float c = d;
#pragma unroll
                    for (int q = 0; q < KNN_K; q++) {
                        float nv = fmaxf(v[q], c);
                        c = fminf(v[q], c);
                        v[q] = nv;
                    }
                }
            }
        }
        sTau[pp] = v[KNN_K - 1];
    }
    __syncthreads();

    // ---- Phase B: rescan, collect j with d >= tau ----
    {
        const float tau = sTau[pp];
#pragma unroll 4
        for (int jj = 0; jj < SEGLEN; jj++) {
            int j = j0 + jj;
            float4 p4 = sP[j];
            float d = c0 * p4.x;
            d = fmaf(c1, p4.y, d);
            d = fmaf(c2, p4.z, d);
            d = 2.0f * d - cxx - p4.w;
            if (d >= tau) {
                int pos = atomicAdd(&sCnt[pp], 1);
                if (pos < CAND_CAP) {
                    sCd[pp * CAND_CAP + pos] = d;
                    sCj[pp * CAND_CAP + pos] = j;
                }
            }
        }
    }
    __syncthreads();

    // ---- rank-based exact selection: top-20 by (d desc, j asc) ----
    for (int v2 = t; v2 < KNN_PPB * CAND_CAP; v2 += KNN_THR) {
        int pq = v2 >> 5;
        int q  = v2 & 31;
        int cnt = sCnt[pq];
        if (cnt > CAND_CAP) cnt = CAND_CAP;
        if (q < cnt) {
            const float* cd = sCd + pq * CAND_CAP;
            const int*   cj = sCj + pq * CAND_CAP;
            float d = cd[q]; int j = cj[q];
            int rank = 0;
            for (int q2 = 0; q2 < cnt; q2++) {
                float d2 = cd[q2]; int j2 = cj[q2];
                rank += ((d2 > d) || (d2 == d && j2 < j)) ? 1 : 0;
            }
            if (rank < KNN_K) {
                g_knn[((size_t)b * NPTS + (chunk << 6) + pq) * KNN_K + rank] = j;
            }
        }
    }
}

// ===========================================================================
// Kernel 2: PERSISTENT fused edge kernel (148 blocks x 768 threads).
// W1 a-weights stored PRE-DUPLICATED as f32x2 in smem (no dup2 MOVs in the
// inner loop); b-weights compact (float2 + float) for the scalar qv.
// G-form c-folded bilinear GEMM: thread = (pt, o), all 20 k.
// ===========================================================================
#define PTS 12
#define THR 768
#define NTILES ((NPOINTS + PTS - 1) / PTS)   // 1366
#define EDGE_GRID 148

#define EPAD 9

#define F_WA2  0                        // [3][64p][64o] x u64(dup) = 24576 fl
#define F_WB01 (F_WA2 + 24576)          // [64p][64o] float2 {b0,b1} = 8192
#define F_WB2  (F_WB01 + 8192)          // [64p][64o] float b2 = 4096
#define F_Y    (F_WB2 + 4096)           // [12pt][64p][20k] = 15360
#define F_E    (F_Y + 15360)            // [12*20][9] = 2160
#define F_W0   (F_E + 2160)             // 384
#define F_B0S  (F_W0 + 384)
#define F_B0B  (F_B0S + 64)
#define F_B1S  (F_B0B + 64)
#define F_B1B  (F_B1S + 64)
#define F_WC   (F_B1B + 64)             // 192
#define F_BNC  (F_WC + 192)             // 8
#define F_X1   (F_BNC + 8)              // 768
#define SMEM_FLOATS (F_X1 + 768)
#define SMEM_BYTES (SMEM_FLOATS * 4)

__global__ __launch_bounds__(THR, 1) void edge_kernel(
    const float* __restrict__ x,
    const float* __restrict__ W0,
    const float* __restrict__ bn0_s, const float* __restrict__ bn0_b,
    const float* __restrict__ W1,
    const float* __restrict__ bn1_s, const float* __restrict__ bn1_b,
    const float* __restrict__ Wc,
    const float* __restrict__ bnc_s, const float* __restrict__ bnc_b,
    float* __restrict__ outp)
{
    extern __shared__ float sm[];
    float* sWa2  = sm + F_WA2;
    float* sWb01 = sm + F_WB01;
    float* sWb2  = sm + F_WB2;
    float* sY    = sm + F_Y;
    float* sE    = sm + F_E;
    float* sW0   = sm + F_W0;
    float* sB0s  = sm + F_B0S;
    float* sB0b  = sm + F_B0B;
    float* sB1s  = sm + F_B1S;
    float* sB1b  = sm + F_B1B;
    float* sWc   = sm + F_WC;
    float* sBnc  = sm + F_BNC;
    float* sX1   = sm + F_X1;

    const int t = threadIdx.x;

    // ---- one-time staging: W1 row (oo*6+ii), col p ----
    for (int g = t; g < ROWS * CO; g += THR) {
        int q = g >> 6;
        int p = g & 63;
        int oo = q / 6;
        int ii = q - oo * 6;
        float w = W1[g];
        if (ii < 3) {
            int idx = (ii * 4096 + p * 64 + oo) * 2;
            sWa2[idx] = w;
            sWa2[idx + 1] = w;
        } else if (ii < 5) {
            sWb01[(p * 64 + oo) * 2 + (ii - 3)] = w;
        } else {
            sWb2[p * 64 + oo] = w;
        }
    }
    if (t < 384) sW0[t] = W0[t];
    if (t < 64) {
        sB0s[t] = bn0_s[t]; sB0b[t] = bn0_b[t];
        sB1s[t] = bn1_s[t]; sB1b[t] = bn1_b[t];
    }
    if (t < 192) sWc[t] = Wc[t];
    if (t < 3) { sBnc[t] = bnc_s[t]; sBnc[4 + t] = bnc_b[t]; }

    const int pt_g = t >> 6;
    const int o    = t & 63;

    for (int tile = blockIdx.x; tile < NTILES; tile += EDGE_GRID) {
        __syncthreads();

        // ---- edge features ----
        if (t < PTS * KNN_K) {
            int pt = t / KNN_K, k = t - pt * KNN_K;
            int gp = tile * PTS + pt;
            float e0 = 0.f, e1 = 0.f, e2 = 0.f, c0 = 0.f, c1 = 0.f, c2 = 0.f;
            if (gp < NPOINTS) {
                int b = gp >> 11, n = gp & (NPTS - 1);
                const float* xb = x + (size_t)b * 3 * NPTS;
                c0 = xb[n]; c1 = xb[NPTS + n]; c2 = xb[2 * NPTS + n];
                int j = g_knn[((size_t)b * NPTS + n) * KNN_K + k];
                e0 = xb[j] - c0;
                e1 = xb[NPTS + j] - c1;
                e2 = xb[2 * NPTS + j] - c2;
            }
            float* e = sE + t * EPAD;
            e[0] = e0; e[1] = e1; e[2] = e2;
            e[3] = c0; e[4] = c1; e[5] = c2;
        }
        __syncthreads();

        // ---- MLP0: y[pt][p][k] ----
        for (int v = t; v < PTS * CO * KNN_K; v += THR) {
            int pt = v / (CO * KNN_K);
            int rem = v - pt * (CO * KNN_K);
            int p = rem / KNN_K;
            int k = rem - p * KNN_K;
            const float* e = sE + (pt * KNN_K + k) * EPAD;
            const float* w = sW0 + p * 6;
            float d = e[0] * w[0];
            d = fmaf(e[1], w[1], d);
            d = fmaf(e[2], w[2], d);
            d = fmaf(e[3], w[3], d);
            d = fmaf(e[4], w[4], d);
            d = fmaf(e[5], w[5], d);
            float yv = fmaf(d, sB0s[p], sB0b[p]);
            yv = (yv >= 0.0f) ? yv : NEG_SLOPE * yv;
            sY[v] = yv;
        }
        __syncthreads();

        // ---- main GEMM: thread = (pt, o), 20 k ----
        {
            const float* ept = sE + (pt_g * KNN_K) * EPAD;
            const float cc0 = ept[3], cc1 = ept[4], cc2 = ept[5];
            float maxv = -INFINITY;

#pragma unroll
            for (int half = 0; half < 2; half++) {
                u64 g0[5], g1[5], g2[5], gq[5];
#pragma unroll
                for (int q = 0; q < 5; q++) { g0[q] = 0; g1[q] = 0; g2[q] = 0; gq[q] = 0; }

                const float* yb = sY + (pt_g * CO) * KNN_K + half * 10;

#pragma unroll 2
                for (int p = 0; p < CO; p++) {
                    const u64* wa = (const u64*)sWa2 + p * 64 + o;
                    u64 a0d = wa[0];
                    u64 a1d = wa[4096];
                    u64 a2d = wa[8192];
                    float2 b01 = *(const float2*)(sWb01 + (p * 64 + o) * 2);
                    float b2v = sWb2[p * 64 + o];
                    float qv = b01.x * cc0;
                    qv = fmaf(b01.y, cc1, qv);
                    qv = fmaf(b2v, cc2, qv);
                    u64 qd = dup2(qv);

                    const u64* yp = (const u64*)(yb + p * KNN_K);
                    u64 y0 = yp[0], y1 = yp[1], y2 = yp[2], y3 = yp[3], y4 = yp[4];

                    ffma2(g0[0], y0, a0d); ffma2(g1[0], y0, a1d); ffma2(g2[0], y0, a2d); ffma2(gq[0], y0, qd);
                    ffma2(g0[1], y1, a0d); ffma2(g1[1], y1, a1d); ffma2(g2[1], y1, a2d); ffma2(gq[1], y1, qd);
                    ffma2(g0[2], y2, a0d); ffma2(g1[2], y2, a1d); ffma2(g2[2], y2, a2d); ffma2(gq[2], y2, qd);
                    ffma2(g0[3], y3, a0d); ffma2(g1[3], y3, a1d); ffma2(g2[3], y3, a2d); ffma2(gq[3], y3, qd);
                    ffma2(g0[4], y4, a0d); ffma2(g1[4], y4, a1d); ffma2(g2[4], y4, a2d); ffma2(gq[4], y4, qd);
                }

#pragma unroll
                for (int q = 0; q < 5; q++) {
                    const float* r0 = ept + (half * 10 + 2 * q) * EPAD;
                    const float* r1 = r0 + EPAD;
                    u64 d0 = pack2(r0[0], r1[0]);
                    u64 d1 = pack2(r0[1], r1[1]);
                    u64 d2 = pack2(r0[2], r1[2]);
                    u64 acc = gq[q];
                    ffma2(acc, d0, g0[q]);
                    ffma2(acc, d1, g1[q]);
                    ffma2(acc, d2, g2[q]);
                    float lo, hi;
                    unpack2(lo, hi, acc);
                    maxv = fmaxf(maxv, lo);
                    maxv = fmaxf(maxv, hi);
                }
            }

            float vv = fmaf(maxv, sB1s[o], sB1b[o]);
            vv = (vv >= 0.0f) ? vv : NEG_SLOPE * vv;
            sX1[pt_g * 64 + o] = vv;
        }
        __syncthreads();

        // ---- head ----
        if (t < PTS * 3) {
            int pt = t / 3, c = t - pt * 3;
            int gp = tile * PTS + pt;
            if (gp < NPOINTS) {
                int b = gp >> 11, n = gp & (NPTS - 1);
                const float* x1 = sX1 + pt * 64;
                const float* w = sWc + c * 64;
                float d = 0.0f;
#pragma unroll
                for (int oo = 0; oo < 64; oo++) d = fmaf(x1[oo], w[oo], d);
                float z = fmaf(d, sBnc[c], sBnc[4 + c]);
                z = (z >= 0.0f) ? z : NEG_SLOPE * z;
                outp[((size_t)b * 3 + c) * NPTS + n] = z;
            }
        }
    }
}

// ---------------------------------------------------------------------------
extern "C" void kernel_launch(void* const* d_in, const int* in_sizes, int n_in,
                              void* d_out, int out_size)
{
    const float* x     = (const float*)d_in[0];
    const float* W0    = (const float*)d_in[1];
    const float* bn0_s = (const float*)d_in[2];
    const float* bn0_b = (const float*)d_in[3];
    const float* W1    = (const float*)d_in[4];
    const float* bn1_s = (const float*)d_in[5];
    const float* bn1_b = (const float*)d_in[6];
    const float* Wc    = (const float*)d_in[7];
    const float* bnc_s = (const float*)d_in[8];
    const float* bnc_b = (const float*)d_in[9];
    float* outp = (float*)d_out;

    cudaFuncSetAttribute(knn_kernel,
                         cudaFuncAttributeMaxDynamicSharedMemorySize, KNN_SMEM_BYTES);
    cudaFuncSetAttribute(edge_kernel,
                         cudaFuncAttributeMaxDynamicSharedMemorySize, SMEM_BYTES);

    knn_kernel<<<NPOINTS / KNN_PPB, KNN_THR, KNN_SMEM_BYTES>>>(x);
    edge_kernel<<<EDGE_GRID, THR, SMEM_BYTES>>>(
        x, W0, bn0_s, bn0_b, W1, bn1_s, bn1_b, Wc, bnc_s, bnc_b, outp);
}

// round 13
// speedup vs baseline: 1.0001x; 1.0001x over previous
#include <cuda_runtime.h>
#include <math.h>
#include <stdint.h>

#define NEG_SLOPE 0.2f
#define KNN_K 20
#define BATCH 8
#define NPTS 2048
#define CO 64
#define CIN 6
#define ROWS 384
#define NPOINTS (BATCH * NPTS)

__device__ int g_knn[NPOINTS * KNN_K];

typedef unsigned long long u64;

__device__ __forceinline__ void ffma2(u64& d, u64 a, u64 b) {
    asm("fma.rn.f32x2 %0, %1, %2, %0;" : "+l"(d) : "l"(a), "l"(b));
}
__device__ __forceinline__ u64 dup2(float w) {
    u64 r; asm("mov.b64 %0, {%1, %1};" : "=l"(r) : "f"(w)); return r;
}
__device__ __forceinline__ u64 pack2(float lo, float hi) {
    u64 r; asm("mov.b64 %0, {%1, %2};" : "=l"(r) : "f"(lo), "f"(hi)); return r;
}
__device__ __forceinline__ void unpack2(float& lo, float& hi, u64 v) {
    asm("mov.b64 {%0, %1}, %2;" : "=f"(lo), "=f"(hi) : "l"(v));
}

// ===========================================================================
// Kernel 1: KNN. 256 blocks x 512 threads. 64 points/block, 8 segment-threads
// per point (256 j each). Phase A: scalar FMNMX top-20 chain. Merge -> tau.
// Phase B: rescan collect. Rank-based parallel exact selection.
// ===========================================================================
#define KNN_THR 512
#define KNN_PPB 64
#define KSEG 8
#define SEGLEN (NPTS / KSEG)          // 256
#define CAND_CAP 32

#define KOFF_P     0                                      // float4[2048] = 8192
#define KOFF_LIST  (NPTS * 4)                             // [64][8][20] = 10240
#define KOFF_TAU   (KOFF_LIST + KNN_PPB * KSEG * KNN_K)   // 64
#define KOFF_CNT   (KOFF_TAU + KNN_PPB)                   // 64
#define KOFF_CD    (KOFF_CNT + KNN_PPB)                   // [64][32]
#define KOFF_CJ    (KOFF_CD + KNN_PPB * CAND_CAP)         // [64][32]
#define KNN_SMEM_FLOATS (KOFF_CJ + KNN_PPB * CAND_CAP)
#define KNN_SMEM_BYTES (KNN_SMEM_FLOATS * 4)

__global__ __launch_bounds__(KNN_THR) void knn_kernel(const float* __restrict__ x) {
    extern __shared__ float ksm[];
    float4* sP   = (float4*)(ksm + KOFF_P);
    float* sList = ksm + KOFF_LIST;
    float* sTau  = ksm + KOFF_TAU;
    int*   sCnt  = (int*)(ksm + KOFF_CNT);
    float* sCd   = ksm + KOFF_CD;
    int*   sCj   = (int*)(ksm + KOFF_CJ);

    const int b = blockIdx.x >> 5;
    const int chunk = blockIdx.x & 31;
    const float* xb = x + (size_t)b * 3 * NPTS;

    const int t = threadIdx.x;
    for (int j = t; j < NPTS; j += KNN_THR) {
        float a0 = xb[j], a1 = xb[NPTS + j], a2 = xb[2 * NPTS + j];
        float xx = (a0 * a0 + a1 * a1) + a2 * a2;
        sP[j] = make_float4(a0, a1, a2, xx);
    }
    if (t < KNN_PPB) sCnt[t] = 0;
    __syncthreads();

    const int s  = t >> 6;        // segment 0..7 (warp-uniform)
    const int pp = t & 63;
    const int i  = (chunk << 6) + pp;

    float4 cv = sP[i];
    const float c0 = cv.x, c1 = cv.y, c2 = cv.z, cxx = cv.w;

    // ---- Phase A: value-only sorted top-20 ----
    float v[KNN_K];
#pragma unroll
    for (int k = 0; k < KNN_K; k++) v[k] = -INFINITY;

    const int j0 = s * SEGLEN;
#pragma unroll 4
    for (int jj = 0; jj < SEGLEN; jj++) {
        int j = j0 + jj;
        float4 p4 = sP[j];
        float d = c0 * p4.x;
        d = fmaf(c1, p4.y, d);
        d = fmaf(c2, p4.z, d);
        d = 2.0f * d - cxx - p4.w;
        if (d > v[KNN_K - 1]) {
            float c = d;
#pragma unroll
            for (int k = 0; k < KNN_K; k++) {
                float nv = fmaxf(v[k], c);
                c = fminf(v[k], c);
                v[k] = nv;
            }
        }
    }
    {
        float* lp = sList + (pp * KSEG + s) * KNN_K;
#pragma unroll
        for (int k = 0; k < KNN_K; k++) lp[k] = v[k];
    }
    __syncthreads();

    // ---- merge: seg-0 lanes fold in the other 7 lists -> tau ----
    if (s == 0) {
        for (int ss = 1; ss < KSEG; ss++) {
            const float* lp = sList + (pp * KSEG + ss) * KNN_K;
#pragma unroll
            for (int k = 0; k < KNN_K; k++) {
                float d = lp[k];
                if (d > v[KNN_K - 1]) {
                    float c = d;
#pragma unroll
                    for (int q = 0; q < KNN_K; q++) {
                        float nv = fmaxf(v[q], c);
                        c = fminf(v[q], c);
                        v[q] = nv;
                    }
                }
            }
        }
        sTau[pp] = v[KNN_K - 1];
    }
    __syncthreads();

    // ---- Phase B: rescan, collect j with d >= tau ----
    {
        const float tau = sTau[pp];
#pragma unroll 4
        for (int jj = 0; jj < SEGLEN; jj++) {
            int j = j0 + jj;
            float4 p4 = sP[j];
            float d = c0 * p4.x;
            d = fmaf(c1, p4.y, d);
            d = fmaf(c2, p4.z, d);
            d = 2.0f * d - cxx - p4.w;
            if (d >= tau) {
                int pos = atomicAdd(&sCnt[pp], 1);
                if (pos < CAND_CAP) {
                    sCd[pp * CAND_CAP + pos] = d;
                    sCj[pp * CAND_CAP + pos] = j;
                }
            }
        }
    }
    __syncthreads();

    // ---- rank-based exact selection: top-20 by (d desc, j asc) ----
    for (int v2 = t; v2 < KNN_PPB * CAND_CAP; v2 += KNN_THR) {
        int pq = v2 >> 5;
        int q  = v2 & 31;
        int cnt = sCnt[pq];
        if (cnt > CAND_CAP) cnt = CAND_CAP;
        if (q < cnt) {
            const float* cd = sCd + pq * CAND_CAP;
            const int*   cj = sCj + pq * CAND_CAP;
            float d = cd[q]; int j = cj[q];
            int rank = 0;
            for (int q2 = 0; q2 < cnt; q2++) {
                float d2 = cd[q2]; int j2 = cj[q2];
                rank += ((d2 > d) || (d2 == d && j2 < j)) ? 1 : 0;
            }
            if (rank < KNN_K) {
                g_knn[((size_t)b * NPTS + (chunk << 6) + pq) * KNN_K + rank] = j;
            }
        }
    }
}

// ===========================================================================
// Kernel 2: PERSISTENT fused edge kernel (148 blocks x 1024 threads).
// R11 layout (quad+pair W1, float4 y rows), PTS scaled 12->16 for 8 warps/SMSP.
// G-form c-folded bilinear GEMM (f32x2): thread = (pt, o), all 20 k.
// ===========================================================================
#define PTS 16
#define THR 1024
#define NTILES ((NPOINTS + PTS - 1) / PTS)   // 1024
#define EDGE_GRID 148

#define EPAD 9
#define YROW 24        // [half][12], 10 used per half; 16B-aligned rows

#define F_WQ   0                        // [64p][64o][4] = {a0,a1,a2,b0} 16384
#define F_WB   (F_WQ + 16384)           // [64p][64o][2] = {b1,b2}        8192
#define F_Y    (F_WB + 8192)            // [16pt][64p][24] = 24576
#define F_E    (F_Y + 24576)            // [16*20][9] = 2880
#define F_W0   (F_E + 2880)             // 384
#define F_B0S  (F_W0 + 384)
#define F_B0B  (F_B0S + 64)
#define F_B1S  (F_B0B + 64)
#define F_B1B  (F_B1S + 64)
#define F_WC   (F_B1B + 64)             // 192
#define F_BNC  (F_WC + 192)             // 8
#define F_X1   (F_BNC + 8)              // 1024
#define SMEM_FLOATS (F_X1 + 1024)
#define SMEM_BYTES (SMEM_FLOATS * 4)

__global__ __launch_bounds__(THR, 1) void edge_kernel(
    const float* __restrict__ x,
    const float* __restrict__ W0,
    const float* __restrict__ bn0_s, const float* __restrict__ bn0_b,
    const float* __restrict__ W1,
    const float* __restrict__ bn1_s, const float* __restrict__ bn1_b,
    const float* __restrict__ Wc,
    const float* __restrict__ bnc_s, const float* __restrict__ bnc_b,
    float* __restrict__ outp)
{
    extern __shared__ float sm[];
    float* sWq  = sm + F_WQ;
    float* sWb  = sm + F_WB;
    float* sY   = sm + F_Y;
    float* sE   = sm + F_E;
    float* sW0  = sm + F_W0;
    float* sB0s = sm + F_B0S;
    float* sB0b = sm + F_B0B;
    float* sB1s = sm + F_B1S;
    float* sB1b = sm + F_B1B;
    float* sWc  = sm + F_WC;
    float* sBnc = sm + F_BNC;
    float* sX1  = sm + F_X1;

    const int t = threadIdx.x;

    // ---- one-time staging: W1 row (oo*6+ii), col p ----
    for (int g = t; g < ROWS * CO; g += THR) {
        int q = g >> 6;
        int p = g & 63;
        int oo = q / 6;
        int ii = q - oo * 6;
        float w = W1[g];
        if (ii < 4)       sWq[(p * 64 + oo) * 4 + ii] = w;        // a0,a1,a2,b0
        else              sWb[(p * 64 + oo) * 2 + (ii - 4)] = w;  // b1,b2
    }
    if (t < 384) sW0[t] = W0[t];
    if (t < 64) {
        sB0s[t] = bn0_s[t]; sB0b[t] = bn0_b[t];
        sB1s[t] = bn1_s[t]; sB1b[t] = bn1_b[t];
    }
    if (t < 192) sWc[t] = Wc[t];
    if (t < 3) { sBnc[t] = bnc_s[t]; sBnc[4 + t] = bnc_b[t]; }

    const int pt_g = t >> 6;
    const int o    = t & 63;

    for (int tile = blockIdx.x; tile < NTILES; tile += EDGE_GRID) {
        __syncthreads();

        // ---- edge features ----
        if (t < PTS * KNN_K) {
            int pt = t / KNN_K, k = t - pt * KNN_K;
            int gp = tile * PTS + pt;
            float e0 = 0.f, e1 = 0.f, e2 = 0.f, c0 = 0.f, c1 = 0.f, c2 = 0.f;
            if (gp < NPOINTS) {
                int b = gp >> 11, n = gp & (NPTS - 1);
                const float* xb = x + (size_t)b * 3 * NPTS;
                c0 = xb[n]; c1 = xb[NPTS + n]; c2 = xb[2 * NPTS + n];
                int j = g_knn[((size_t)b * NPTS + n) * KNN_K + k];
                e0 = xb[j] - c0;
                e1 = xb[NPTS + j] - c1;
                e2 = xb[2 * NPTS + j] - c2;
            }
            float* e = sE + t * EPAD;
            e[0] = e0; e[1] = e1; e[2] = e2;
            e[3] = c0; e[4] = c1; e[5] = c2;
        }
        __syncthreads();

        // ---- MLP0: y -> sY[pt][p][half*12 + kk] ----
        for (int v = t; v < PTS * CO * KNN_K; v += THR) {
            int pt = v / (CO * KNN_K);
            int rem = v - pt * (CO * KNN_K);
            int p = rem / KNN_K;
            int k = rem - p * KNN_K;
            const float* e = sE + (pt * KNN_K + k) * EPAD;
            const float* w = sW0 + p * 6;
            float d = e[0] * w[0];
            d = fmaf(e[1], w[1], d);
            d = fmaf(e[2], w[2], d);
            d = fmaf(e[3], w[3], d);
            d = fmaf(e[4], w[4], d);
            d = fmaf(e[5], w[5], d);
            float yv = fmaf(d, sB0s[p], sB0b[p]);
            yv = (yv >= 0.0f) ? yv : NEG_SLOPE * yv;
            int half = k / 10, kk = k - half * 10;
            sY[(pt * CO + p) * YROW + half * 12 + kk] = yv;
        }
        __syncthreads();

        // ---- main GEMM: thread = (pt, o), 20 k ----
        {
            const float* ept = sE + (pt_g * KNN_K) * EPAD;
            const float cc0 = ept[3], cc1 = ept[4], cc2 = ept[5];
            float maxv = -INFINITY;

            union F4 { float4 v; u64 d[2]; };

#pragma unroll
            for (int half = 0; half < 2; half++) {
                u64 g0[5], g1[5], g2[5], gq[5];
#pragma unroll
                for (int q = 0; q < 5; q++) { g0[q] = 0; g1[q] = 0; g2[q] = 0; gq[q] = 0; }

                const float* yb = sY + (pt_g * CO) * YROW + half * 12;

#pragma unroll 2
                for (int p = 0; p < CO; p++) {
                    float4 wq = *(const float4*)(sWq + (p * 64 + o) * 4);
                    float2 wb = *(const float2*)(sWb + (p * 64 + o) * 2);
                    float qv = wq.w * cc0;
                    qv = fmaf(wb.x, cc1, qv);
                    qv = fmaf(wb.y, cc2, qv);
                    u64 a0d = dup2(wq.x), a1d = dup2(wq.y), a2d = dup2(wq.z), qd = dup2(qv);

                    const float* yrow = yb + p * YROW;
                    F4 ya, ybv;
                    ya.v  = *(const float4*)(yrow);
                    ybv.v = *(const float4*)(yrow + 4);
                    u64 y4 = *(const u64*)(yrow + 8);
                    u64 y0 = ya.d[0], y1 = ya.d[1], y2 = ybv.d[0], y3 = ybv.d[1];

                    ffma2(g0[0], y0, a0d); ffma2(g1[0], y0, a1d); ffma2(g2[0], y0, a2d); ffma2(gq[0], y0, qd);
                    ffma2(g0[1], y1, a0d); ffma2(g1[1], y1, a1d); ffma2(g2[1], y1, a2d); ffma2(gq[1], y1, qd);
                    ffma2(g0[2], y2, a0d); ffma2(g1[2], y2, a1d); ffma2(g2[2], y2, a2d); ffma2(gq[2], y2, qd);
                    ffma2(g0[3], y3, a0d); ffma2(g1[3], y3, a1d); ffma2(g2[3], y3, a2d); ffma2(gq[3], y3, qd);
                    ffma2(g0[4], y4, a0d); ffma2(g1[4], y4, a1d); ffma2(g2[4], y4, a2d); ffma2(gq[4], y4, qd);
                }

#pragma unroll
                for (int q = 0; q < 5; q++) {
                    const float* r0 = ept + (half * 10 + 2 * q) * EPAD;
                    const float* r1 = r0 + EPAD;
                    u64 d0 = pack2(r0[0], r1[0]);
                    u64 d1 = pack2(r0[1], r1[1]);
                    u64 d2 = pack2(r0[2], r1[2]);
                    u64 acc = gq[q];
                    ffma2(acc, d0, g0[q]);
                    ffma2(acc, d1, g1[q]);
                    ffma2(acc, d2, g2[q]);
                    float lo, hi;
                    unpack2(lo, hi, acc);
                    maxv = fmaxf(maxv, lo);
                    maxv = fmaxf(maxv, hi);
                }
            }

            float vv = fmaf(maxv, sB1s[o], sB1b[o]);
            vv = (vv >= 0.0f) ? vv : NEG_SLOPE * vv;
            sX1[pt_g * 64 + o] = vv;
        }
        __syncthreads();

        // ---- head ----
        if (t < PTS * 3) {
            int pt = t / 3, c = t - pt * 3;
            int gp = tile * PTS + pt;
            if (gp < NPOINTS) {
                int b = gp >> 11, n = gp & (NPTS - 1);
                const float* x1 = sX1 + pt * 64;
                const float* w = sWc + c * 64;
                float d = 0.0f;
#pragma unroll
                for (int oo = 0; oo < 64; oo++) d = fmaf(x1[oo], w[oo], d);
                float z = fmaf(d, sBnc[c], sBnc[4 + c]);
                z = (z >= 0.0f) ? z : NEG_SLOPE * z;
                outp[((size_t)b * 3 + c) * NPTS + n] = z;
            }
        }
    }
}

// ---------------------------------------------------------------------------
extern "C" void kernel_launch(void* const* d_in, const int* in_sizes, int n_in,
                              void* d_out, int out_size)
{
    const float* x     = (const float*)d_in[0];
    const float* W0    = (const float*)d_in[1];
    const float* bn0_s = (const float*)d_in[2];
    const float* bn0_b = (const float*)d_in[3];
    const float* W1    = (const float*)d_in[4];
    const float* bn1_s = (const float*)d_in[5];
    const float* bn1_b = (const float*)d_in[6];
    const float* Wc    = (const float*)d_in[7];
    const float* bnc_s = (const float*)d_in[8];
    const float* bnc_b = (const float*)d_in[9];
    float* outp = (float*)d_out;

    cudaFuncSetAttribute(knn_kernel,
                         cudaFuncAttributeMaxDynamicSharedMemorySize, KNN_SMEM_BYTES);
    cudaFuncSetAttribute(edge_kernel,
                         cudaFuncAttributeMaxDynamicSharedMemorySize, SMEM_BYTES);

    knn_kernel<<<NPOINTS / KNN_PPB, KNN_THR, KNN_SMEM_BYTES>>>(x);
    edge_kernel<<<EDGE_GRID, THR, SMEM_BYTES>>>(
        x, W0, bn0_s, bn0_b, W1, bn1_s, bn1_b, Wc, bnc_s, bnc_b, outp);
}

// round 14
// speedup vs baseline: 1.1953x; 1.1952x over previous
#include <cuda_runtime.h>
#include <math.h>
#include <stdint.h>

#define NEG_SLOPE 0.2f
#define KNN_K 20
#define BATCH 8
#define NPTS 2048
#define CO 64
#define CIN 6
#define ROWS 384
#define NPOINTS (BATCH * NPTS)

__device__ int g_knn[NPOINTS * KNN_K];

typedef unsigned long long u64;

__device__ __forceinline__ void ffma2(u64& d, u64 a, u64 b) {
    asm("fma.rn.f32x2 %0, %1, %2, %0;" : "+l"(d) : "l"(a), "l"(b));
}
__device__ __forceinline__ u64 dup2(float w) {
    u64 r; asm("mov.b64 %0, {%1, %1};" : "=l"(r) : "f"(w)); return r;
}
__device__ __forceinline__ u64 pack2(float lo, float hi) {
    u64 r; asm("mov.b64 %0, {%1, %2};" : "=l"(r) : "f"(lo), "f"(hi)); return r;
}
__device__ __forceinline__ void unpack2(float& lo, float& hi, u64 v) {
    asm("mov.b64 {%0, %1}, %2;" : "=f"(lo), "=f"(hi) : "l"(v));
}

// ===========================================================================
// Kernel 1: KNN (unchanged from R11 best). 256 blocks x 512 threads.
// ===========================================================================
#define KNN_THR 512
#define KNN_PPB 64
#define KSEG 8
#define SEGLEN (NPTS / KSEG)          // 256
#define CAND_CAP 32

#define KOFF_P     0
#define KOFF_LIST  (NPTS * 4)
#define KOFF_TAU   (KOFF_LIST + KNN_PPB * KSEG * KNN_K)
#define KOFF_CNT   (KOFF_TAU + KNN_PPB)
#define KOFF_CD    (KOFF_CNT + KNN_PPB)
#define KOFF_CJ    (KOFF_CD + KNN_PPB * CAND_CAP)
#define KNN_SMEM_FLOATS (KOFF_CJ + KNN_PPB * CAND_CAP)
#define KNN_SMEM_BYTES (KNN_SMEM_FLOATS * 4)

__global__ __launch_bounds__(KNN_THR) void knn_kernel(const float* __restrict__ x) {
    extern __shared__ float ksm[];
    float4* sP   = (float4*)(ksm + KOFF_P);
    float* sList = ksm + KOFF_LIST;
    float* sTau  = ksm + KOFF_TAU;
    int*   sCnt  = (int*)(ksm + KOFF_CNT);
    float* sCd   = ksm + KOFF_CD;
    int*   sCj   = (int*)(ksm + KOFF_CJ);

    const int b = blockIdx.x >> 5;
    const int chunk = blockIdx.x & 31;
    const float* xb = x + (size_t)b * 3 * NPTS;

    const int t = threadIdx.x;
    for (int j = t; j < NPTS; j += KNN_THR) {
        float a0 = xb[j], a1 = xb[NPTS + j], a2 = xb[2 * NPTS + j];
        float xx = (a0 * a0 + a1 * a1) + a2 * a2;
        sP[j] = make_float4(a0, a1, a2, xx);
    }
    if (t < KNN_PPB) sCnt[t] = 0;
    __syncthreads();

    const int s  = t >> 6;
    const int pp = t & 63;
    const int i  = (chunk << 6) + pp;

    float4 cv = sP[i];
    const float c0 = cv.x, c1 = cv.y, c2 = cv.z, cxx = cv.w;

    float v[KNN_K];
#pragma unroll
    for (int k = 0; k < KNN_K; k++) v[k] = -INFINITY;

    const int j0 = s * SEGLEN;
#pragma unroll 4
    for (int jj = 0; jj < SEGLEN; jj++) {
        int j = j0 + jj;
        float4 p4 = sP[j];
        float d = c0 * p4.x;
        d = fmaf(c1, p4.y, d);
        d = fmaf(c2, p4.z, d);
        d = 2.0f * d - cxx - p4.w;
        if (d > v[KNN_K - 1]) {
            float c = d;
#pragma unroll
            for (int k = 0; k < KNN_K; k++) {
                float nv = fmaxf(v[k], c);
                c = fminf(v[k], c);
                v[k] = nv;
            }
        }
    }
    {
        float* lp = sList + (pp * KSEG + s) * KNN_K;
#pragma unroll
        for (int k = 0; k < KNN_K; k++) lp[k] = v[k];
    }
    __syncthreads();

    if (s == 0) {
        for (int ss = 1; ss < KSEG; ss++) {
            const float* lp = sList + (pp * KSEG + ss) * KNN_K;
#pragma unroll
            for (int k = 0; k < KNN_K; k++) {
                float d = lp[k];
                if (d > v[KNN_K - 1]) {
                    float c = d;
#pragma unroll
                    for (int q = 0; q < KNN_K; q++) {
                        float nv = fmaxf(v[q], c);
                        c = fminf(v[q], c);
                        v[q] = nv;
                    }
                }
            }
        }
        sTau[pp] = v[KNN_K - 1];
    }
    __syncthreads();

    {
        const float tau = sTau[pp];
#pragma unroll 4
        for (int jj = 0; jj < SEGLEN; jj++) {
            int j = j0 + jj;
            float4 p4 = sP[j];
            float d = c0 * p4.x;
            d = fmaf(c1, p4.y, d);
            d = fmaf(c2, p4.z, d);
            d = 2.0f * d - cxx - p4.w;
            if (d >= tau) {
                int pos = atomicAdd(&sCnt[pp], 1);
                if (pos < CAND_CAP) {
                    sCd[pp * CAND_CAP + pos] = d;
                    sCj[pp * CAND_CAP + pos] = j;
                }
            }
        }
    }
    __syncthreads();

    for (int v2 = t; v2 < KNN_PPB * CAND_CAP; v2 += KNN_THR) {
        int pq = v2 >> 5;
        int q  = v2 & 31;
        int cnt = sCnt[pq];
        if (cnt > CAND_CAP) cnt = CAND_CAP;
        if (q < cnt) {
            const float* cd = sCd + pq * CAND_CAP;
            const int*   cj = sCj + pq * CAND_CAP;
            float d = cd[q]; int j = cj[q];
            int rank = 0;
            for (int q2 = 0; q2 < cnt; q2++) {
                float d2 = cd[q2]; int j2 = cj[q2];
                rank += ((d2 > d) || (d2 == d && j2 < j)) ? 1 : 0;
            }
            if (rank < KNN_K) {
                g_knn[((size_t)b * NPTS + (chunk << 6) + pq) * KNN_K + rank] = j;
            }
        }
    }
}

// ===========================================================================
// Kernel 2: PERSISTENT fused edge kernel (148 blocks x 512 threads, PTS=8).
// WHOLE-K single p-pass: 40 u64 G-accumulators, W1 loaded ONCE per p.
// thread = (pt, o); quad+pair W1 layout; float4 broadcast y loads.
// ===========================================================================
#define PTS 8
#define THR 512
#define NTILES ((NPOINTS + PTS - 1) / PTS)   // 2048
#define EDGE_GRID 148

#define EPAD 9
#define YROW 24        // [half][12], 10 used per half; 16B-aligned rows

#define F_WQ   0                        // [64p][64o][4] = {a0,a1,a2,b0} 16384
#define F_WB   (F_WQ + 16384)           // [64p][64o][2] = {b1,b2}        8192
#define F_Y    (F_WB + 8192)            // [8pt][64p][24] = 12288
#define F_E    (F_Y + 12288)            // [8*20][9] = 1440
#define F_W0   (F_E + 1440)             // 384
#define F_B0S  (F_W0 + 384)
#define F_B0B  (F_B0S + 64)
#define F_B1S  (F_B0B + 64)
#define F_B1B  (F_B1S + 64)
#define F_WC   (F_B1B + 64)             // 192
#define F_BNC  (F_WC + 192)             // 8
#define F_X1   (F_BNC + 8)              // 512
#define SMEM_FLOATS (F_X1 + 512)
#define SMEM_BYTES (SMEM_FLOATS * 4)

__global__ __launch_bounds__(THR, 1) void edge_kernel(
    const float* __restrict__ x,
    const float* __restrict__ W0,
    const float* __restrict__ bn0_s, const float* __restrict__ bn0_b,
    const float* __restrict__ W1,
    const float* __restrict__ bn1_s, const float* __restrict__ bn1_b,
    const float* __restrict__ Wc,
    const float* __restrict__ bnc_s, const float* __restrict__ bnc_b,
    float* __restrict__ outp)
{
    extern __shared__ float sm[];
    float* sWq  = sm + F_WQ;
    float* sWb  = sm + F_WB;
    float* sY   = sm + F_Y;
    float* sE   = sm + F_E;
    float* sW0  = sm + F_W0;
    float* sB0s = sm + F_B0S;
    float* sB0b = sm + F_B0B;
    float* sB1s = sm + F_B1S;
    float* sB1b = sm + F_B1B;
    float* sWc  = sm + F_WC;
    float* sBnc = sm + F_BNC;
    float* sX1  = sm + F_X1;

    const int t = threadIdx.x;

    // ---- one-time staging ----
    for (int g = t; g < ROWS * CO; g += THR) {
        int q = g >> 6;
        int p = g & 63;
        int oo = q / 6;
        int ii = q - oo * 6;
        float w = W1[g];
        if (ii < 4)       sWq[(p * 64 + oo) * 4 + ii] = w;
        else              sWb[(p * 64 + oo) * 2 + (ii - 4)] = w;
    }
    if (t < 384) sW0[t] = W0[t];
    if (t < 64) {
        sB0s[t] = bn0_s[t]; sB0b[t] = bn0_b[t];
        sB1s[t] = bn1_s[t]; sB1b[t] = bn1_b[t];
    }
    if (t < 192) sWc[t] = Wc[t];
    if (t < 3) { sBnc[t] = bnc_s[t]; sBnc[4 + t] = bnc_b[t]; }

    const int pt_g = t >> 6;
    const int o    = t & 63;

    for (int tile = blockIdx.x; tile < NTILES; tile += EDGE_GRID) {
        __syncthreads();

        // ---- edge features ----
        if (t < PTS * KNN_K) {
            int pt = t / KNN_K, k = t - pt * KNN_K;
            int gp = tile * PTS + pt;
            float e0 = 0.f, e1 = 0.f, e2 = 0.f, c0 = 0.f, c1 = 0.f, c2 = 0.f;
            if (gp < NPOINTS) {
                int b = gp >> 11, n = gp & (NPTS - 1);
                const float* xb = x + (size_t)b * 3 * NPTS;
                c0 = xb[n]; c1 = xb[NPTS + n]; c2 = xb[2 * NPTS + n];
                int j = g_knn[((size_t)b * NPTS + n) * KNN_K + k];
                e0 = xb[j] - c0;
                e1 = xb[NPTS + j] - c1;
                e2 = xb[2 * NPTS + j] - c2;
            }
            float* e = sE + t * EPAD;
            e[0] = e0; e[1] = e1; e[2] = e2;
            e[3] = c0; e[4] = c1; e[5] = c2;
        }
        __syncthreads();

        // ---- MLP0: y -> sY[pt][p][half*12 + kk] ----
        for (int v = t; v < PTS * CO * KNN_K; v += THR) {
            int pt = v / (CO * KNN_K);
            int rem = v - pt * (CO * KNN_K);
            int p = rem / KNN_K;
            int k = rem - p * KNN_K;
            const float* e = sE + (pt * KNN_K + k) * EPAD;
            const float* w = sW0 + p * 6;
            float d = e[0] * w[0];
            d = fmaf(e[1], w[1], d);
            d = fmaf(e[2], w[2], d);
            d = fmaf(e[3], w[3], d);
            d = fmaf(e[4], w[4], d);
            d = fmaf(e[5], w[5], d);
            float yv = fmaf(d, sB0s[p], sB0b[p]);
            yv = (yv >= 0.0f) ? yv : NEG_SLOPE * yv;
            int half = k / 10, kk = k - half * 10;
            sY[(pt * CO + p) * YROW + half * 12 + kk] = yv;
        }
        __syncthreads();

        // ---- main GEMM: thread = (pt, o), ALL 20 k in one p-pass ----
        {
            const float* ept = sE + (pt_g * KNN_K) * EPAD;
            const float cc0 = ept[3], cc1 = ept[4], cc2 = ept[5];

            union F4 { float4 v; u64 d[2]; };

            u64 g0[10], g1[10], g2[10], gq[10];
#pragma unroll
            for (int q = 0; q < 10; q++) { g0[q] = 0; g1[q] = 0; g2[q] = 0; gq[q] = 0; }

            const float* yb = sY + (pt_g * CO) * YROW;

#pragma unroll 1
            for (int p = 0; p < CO; p++) {
                float4 wq = *(const float4*)(sWq + (p * 64 + o) * 4);
                float2 wb = *(const float2*)(sWb + (p * 64 + o) * 2);
                float qv = wq.w * cc0;
                qv = fmaf(wb.x, cc1, qv);
                qv = fmaf(wb.y, cc2, qv);
                u64 a0d = dup2(wq.x), a1d = dup2(wq.y), a2d = dup2(wq.z), qd = dup2(qv);

                const float* yrow = yb + p * YROW;
                F4 h0a, h0b, h1a, h1b;
                h0a.v = *(const float4*)(yrow);
                h0b.v = *(const float4*)(yrow + 4);
                u64 y4 = *(const u64*)(yrow + 8);
                h1a.v = *(const float4*)(yrow + 12);
                h1b.v = *(const float4*)(yrow + 16);
                u64 y9 = *(const u64*)(yrow + 20);

                u64 y[10];
                y[0] = h0a.d[0]; y[1] = h0a.d[1]; y[2] = h0b.d[0]; y[3] = h0b.d[1]; y[4] = y4;
                y[5] = h1a.d[0]; y[6] = h1a.d[1]; y[7] = h1b.d[0]; y[8] = h1b.d[1]; y[9] = y9;

#pragma unroll
                for (int q = 0; q < 10; q++) {
                    ffma2(g0[q], y[q], a0d);
                    ffma2(g1[q], y[q], a1d);
                    ffma2(g2[q], y[q], a2d);
                    ffma2(gq[q], y[q], qd);
                }
            }

            float maxv = -INFINITY;
#pragma unroll
            for (int q = 0; q < 10; q++) {
                const float* r0 = ept + (2 * q) * EPAD;
                const float* r1 = r0 + EPAD;
                u64 d0 = pack2(r0[0], r1[0]);
                u64 d1 = pack2(r0[1], r1[1]);
                u64 d2 = pack2(r0[2], r1[2]);
                u64 acc = gq[q];
                ffma2(acc, d0, g0[q]);
                ffma2(acc, d1, g1[q]);
                ffma2(acc, d2, g2[q]);
                float lo, hi;
                unpack2(lo, hi, acc);
                maxv = fmaxf(maxv, lo);
                maxv = fmaxf(maxv, hi);
            }

            float vv = fmaf(maxv, sB1s[o], sB1b[o]);
            vv = (vv >= 0.0f) ? vv : NEG_SLOPE * vv;
            sX1[pt_g * 64 + o] = vv;
        }
        __syncthreads();

        // ---- head ----
        if (t < PTS * 3) {
            int pt = t / 3, c = t - pt * 3;
            int gp = tile * PTS + pt;
            if (gp < NPOINTS) {
                int b = gp >> 11, n = gp & (NPTS - 1);
                const float* x1 = sX1 + pt * 64;
                const float* w = sWc + c * 64;
                float d = 0.0f;
#pragma unroll
                for (int oo = 0; oo < 64; oo++) d = fmaf(x1[oo], w[oo], d);
                float z = fmaf(d, sBnc[c], sBnc[4 + c]);
                z = (z >= 0.0f) ? z : NEG_SLOPE * z;
                outp[((size_t)b * 3 + c) * NPTS + n] = z;
            }
        }
    }
}

// ---------------------------------------------------------------------------
extern "C" void kernel_launch(void* const* d_in, const int* in_sizes, int n_in,
                              void* d_out, int out_size)
{
    const float* x     = (const float*)d_in[0];
    const float* W0    = (const float*)d_in[1];
    const float* bn0_s = (const float*)d_in[2];
    const float* bn0_b = (const float*)d_in[3];
    const float* W1    = (const float*)d_in[4];
    const float* bn1_s = (const float*)d_in[5];
    const float* bn1_b = (const float*)d_in[6];
    const float* Wc    = (const float*)d_in[7];
    const float* bnc_s = (const float*)d_in[8];
    const float* bnc_b = (const float*)d_in[9];
    float* outp = (float*)d_out;

    cudaFuncSetAttribute(knn_kernel,
                         cudaFuncAttributeMaxDynamicSharedMemorySize, KNN_SMEM_BYTES);
    cudaFuncSetAttribute(edge_kernel,
                         cudaFuncAttributeMaxDynamicSharedMemorySize, SMEM_BYTES);

    knn_kernel<<<NPOINTS / KNN_PPB, KNN_THR, KNN_SMEM_BYTES>>>(x);
    edge_kernel<<<EDGE_GRID, THR, SMEM_BYTES>>>(
        x, W0, bn0_s, bn0_b, W1, bn1_s, bn1_b, Wc, bnc_s, bnc_b, outp);
}